// round 12
// baseline (speedup 1.0000x reference)
#include <cuda_runtime.h>
#include <cuda_bf16.h>
#include <cstdint>
#include <math.h>

// Problem constants
#define Bn   8
#define Cc   192
#define Nn   3136          // H*W
#define Kk   9
#define C2c  384           // 2*C
#define OUTc 192
#define Mrows 25088        // B*N
#define MTILES 196         // Mrows / 128
#define EPSf 1e-5f

// ------------------------- device scratch ----------------------------------
__device__ __align__(16) float          g_xt[Bn * Nn * Cc];
__device__ __align__(16) __nv_bfloat16  g_a1hi[(size_t)Mrows * C2c];
__device__ __align__(16) __nv_bfloat16  g_a1lo[(size_t)Mrows * C2c];
__device__ __align__(16) __nv_bfloat16  g_a2hi[(size_t)Mrows * C2c];
__device__ __align__(16) __nv_bfloat16  g_a2lo[(size_t)Mrows * C2c];
__device__ __align__(16) __nv_bfloat16  g_w1hi[C2c * C2c];
__device__ __align__(16) __nv_bfloat16  g_w1lo[C2c * C2c];
__device__ __align__(16) __nv_bfloat16  g_w2hi[OUTc * C2c];
__device__ __align__(16) __nv_bfloat16  g_w2lo[OUTc * C2c];
__device__ __align__(16) float          g_h1[(size_t)Mrows * C2c];
__device__ __align__(16) float          g_h2[(size_t)Mrows * OUTc];
__device__ float  g_ps[MTILES * C2c];
__device__ float  g_pq[MTILES * C2c];
__device__ float2 g_aff1[C2c];
__device__ float2 g_aff2[OUTc];

__device__ __forceinline__ float gelu_exact(float x) {
    return 0.5f * x * (1.0f + erff(x * 0.70710678118654752f));
}
__device__ __forceinline__ void split_bf16(float v, __nv_bfloat16& hi, __nv_bfloat16& lo) {
    hi = __float2bfloat16(v);
    lo = __float2bfloat16(v - __bfloat162float(hi));
}
// pack two floats: returns hi-pair bits, writes lo-pair bits
__device__ __forceinline__ uint32_t pack2(float a, float b, uint32_t& lobits) {
    __nv_bfloat16 h0, l0, h1, l1;
    split_bf16(a, h0, l0);
    split_bf16(b, h1, l1);
    __nv_bfloat162 H; H.x = h0; H.y = h1;
    __nv_bfloat162 L; L.x = l0; L.y = l1;
    lobits = *reinterpret_cast<uint32_t*>(&L);
    return *reinterpret_cast<uint32_t*>(&H);
}
__device__ __forceinline__ uint32_t smem_u32(const void* p) {
    return (uint32_t)__cvta_generic_to_shared(p);
}
__device__ __forceinline__ void ldsm_x4(uint32_t* r, uint32_t addr) {
    asm volatile("ldmatrix.sync.aligned.m8n8.x4.shared.b16 {%0,%1,%2,%3}, [%4];"
                 : "=r"(r[0]), "=r"(r[1]), "=r"(r[2]), "=r"(r[3]) : "r"(addr));
}
__device__ __forceinline__ void mma16816(float* c, const uint32_t* a, const uint32_t* b) {
    asm volatile(
        "mma.sync.aligned.m16n8k16.row.col.f32.bf16.bf16.f32 "
        "{%0,%1,%2,%3}, {%4,%5,%6,%7}, {%8,%9}, {%0,%1,%2,%3};"
        : "+f"(c[0]), "+f"(c[1]), "+f"(c[2]), "+f"(c[3])
        : "r"(a[0]), "r"(a[1]), "r"(a[2]), "r"(a[3]), "r"(b[0]), "r"(b[1]));
}
#define CP16(dst, src)  asm volatile("cp.async.cg.shared.global [%0], [%1], 16;" :: "r"(dst), "l"(src))
#define CP_COMMIT()     asm volatile("cp.async.commit_group;" ::: "memory")
#define CP_WAIT1()      asm volatile("cp.async.wait_group 1;" ::: "memory")
#define CP_WAIT0()      asm volatile("cp.async.wait_group 0;" ::: "memory")

// ------------------------- transpose x -------------------------------------
__global__ void transpose_x_kernel(const float* __restrict__ x, float* __restrict__ xt) {
    __shared__ float tile[32][33];
    int b  = blockIdx.z;
    int n0 = blockIdx.x * 32;
    int c0 = blockIdx.y * 32;
    int tx = threadIdx.x, ty = threadIdx.y;
    tile[ty][tx] = x[((size_t)b * Cc + c0 + ty) * Nn + n0 + tx];
    __syncthreads();
    xt[((size_t)b * Nn + n0 + ty) * Cc + c0 + tx] = tile[tx][ty];
}

// ------------------------- weight split ------------------------------------
__global__ void split_w_kernel(const float* __restrict__ w, __nv_bfloat16* __restrict__ hi,
                               __nv_bfloat16* __restrict__ lo, int n) {
    int i = blockIdx.x * 256 + threadIdx.x;
    if (i < n) split_bf16(w[i], hi[i], lo[i]);
}

// ------------------------- gather + diff-max + interleave + split ----------
__global__ void __launch_bounds__(256)
gather_kernel(const float* __restrict__ xt, const int* __restrict__ edge,
              __nv_bfloat16* __restrict__ ahi, __nv_bfloat16* __restrict__ alo) {
    int warp = (blockIdx.x * blockDim.x + threadIdx.x) >> 5;
    int lane = threadIdx.x & 31;
    int b = warp / Nn;
    int n = warp % Nn;
    const float* xb = xt + (size_t)b * Nn * Cc;

    float xv[6], mv[6];
#pragma unroll
    for (int j = 0; j < 6; j++) {
        xv[j] = xb[(size_t)n * Cc + lane + 32 * j];
        mv[j] = -3.402823466e38f;
    }
    const int* e0 = edge + ((size_t)b * Nn + n) * Kk;
    const int* e1 = e0 + (size_t)Bn * Nn * Kk;
#pragma unroll
    for (int k = 0; k < Kk; k++) {
        int jn  = __ldg(&e0[k]);
        int in_ = __ldg(&e1[k]);
        const float* rj = xb + (size_t)jn  * Cc;
        const float* ri = xb + (size_t)in_ * Cc;
#pragma unroll
        for (int j = 0; j < 6; j++) {
            int c = lane + 32 * j;
            mv[j] = fmaxf(mv[j], __ldg(&rj[c]) - __ldg(&ri[c]));
        }
    }
    __nv_bfloat162* oh = reinterpret_cast<__nv_bfloat162*>(ahi + (size_t)warp * C2c);
    __nv_bfloat162* ol = reinterpret_cast<__nv_bfloat162*>(alo + (size_t)warp * C2c);
#pragma unroll
    for (int j = 0; j < 6; j++) {
        uint32_t lob;
        uint32_t hib = pack2(xv[j], mv[j], lob);
        oh[lane + 32 * j] = *reinterpret_cast<__nv_bfloat162*>(&hib);
        ol[lane + 32 * j] = *reinterpret_cast<__nv_bfloat162*>(&lob);
    }
}

// ------------------------- pipelined mma.sync GEMM + fused BN stats --------
// C[M,Ndim] = A[M,384] * B[Ndim,384]^T + bias; 3-term bf16 split MMA.
// 2-stage cp.async double buffer. Epilogue emits deterministic per-CTA
// (sum, sumsq) partials over its 128 rows for each of its BN columns.
#define GBK  32
#define LDAe 40              // bf16 elems per smem row (32 + 8 pad)

template <int BN, int WGM, int WGN, int WMT, int WNT, int MINB>
__global__ void __launch_bounds__(256, MINB)
mma_gemm_fused(const __nv_bfloat16* __restrict__ Ahi, const __nv_bfloat16* __restrict__ Alo,
               const __nv_bfloat16* __restrict__ Bhi, const __nv_bfloat16* __restrict__ Blo,
               const float* __restrict__ bias, float* __restrict__ Cout,
               float* __restrict__ ps, float* __restrict__ pq, int Ndim) {
    static_assert(WGM * WGN == 8 && WGM * WMT * 16 == 128 && WGN * WNT * 8 == BN, "cfg");
    static_assert(WNT * 8 == 32, "stats layout assumes 32 cols per warp");
    extern __shared__ __align__(16) char smem[];
    constexpr int AHALF = 128 * LDAe * 2;      // bytes per A half
    constexpr int BHALF = BN  * LDAe * 2;
    constexpr int STAGE = 2 * AHALF + 2 * BHALF;
    constexpr int OFF_STATS = 0;               // float2 [8][32]
    constexpr int OFF_STG   = 2048;
    constexpr int KITERS = C2c / GBK;          // 12

    const int tid  = threadIdx.x;
    const int wid  = tid >> 5;
    const int lane = tid & 31;
    const int wm   = wid / WGN;
    const int wn   = wid % WGN;
    const int m0   = blockIdx.y * 128;
    const int n0   = blockIdx.x * BN;
    const uint32_t sb = smem_u32(smem);

    float acc[WMT][WNT][4];
#pragma unroll
    for (int i = 0; i < WMT; i++)
#pragma unroll
        for (int j = 0; j < WNT; j++)
#pragma unroll
            for (int q = 0; q < 4; q++) acc[i][j][q] = 0.0f;

    const int ar = lane & 15;
    const int ac = (lane >> 4) << 3;
    const int br = (lane & 7) + ((lane >> 4) << 3);
    const int bc = ((lane >> 3) & 1) << 3;

    auto load_stage = [&](int stg, int kb) {
        const uint32_t a_hi = sb + OFF_STG + stg * STAGE;
        const uint32_t a_lo = a_hi + AHALF;
        const uint32_t b_hi = a_hi + 2 * AHALF;
        const uint32_t b_lo = b_hi + BHALF;
#pragma unroll
        for (int i = 0; i < 2; i++) {                       // A: 512 slots
            int idx = tid + 256 * i;
            int row = idx >> 2, c8 = (idx & 3) << 3;
            size_t  go = (size_t)(m0 + row) * C2c + kb + c8;
            uint32_t so = (uint32_t)(row * LDAe + c8) * 2;
            CP16(a_hi + so, Ahi + go);
            CP16(a_lo + so, Alo + go);
        }
#pragma unroll
        for (int i = 0; i < BN * 4 / 256; i++) {            // B: BN*4 slots
            int idx = tid + 256 * i;
            int row = idx >> 2, c8 = (idx & 3) << 3;
            size_t  go = (size_t)(n0 + row) * C2c + kb + c8;
            uint32_t so = (uint32_t)(row * LDAe + c8) * 2;
            CP16(b_hi + so, Bhi + go);
            CP16(b_lo + so, Blo + go);
        }
        CP_COMMIT();
    };

    load_stage(0, 0);

    for (int it = 0; it < KITERS; it++) {
        if (it + 1 < KITERS) {
            load_stage((it + 1) & 1, (it + 1) * GBK);
            CP_WAIT1();
        } else {
            CP_WAIT0();
        }
        __syncthreads();

        const int stg = it & 1;
        const uint32_t a_hi = sb + OFF_STG + stg * STAGE;
        const uint32_t a_lo = a_hi + AHALF;
        const uint32_t b_hi = a_hi + 2 * AHALF;
        const uint32_t b_lo = b_hi + BHALF;

#pragma unroll
        for (int ks = 0; ks < 2; ks++) {
            const int k16 = ks * 16;
            uint32_t ah[WMT][4], al[WMT][4];
#pragma unroll
            for (int mt = 0; mt < WMT; mt++) {
                int row = wm * WMT * 16 + mt * 16 + ar;
                uint32_t off = (uint32_t)(row * LDAe + k16 + ac) * 2;
                ldsm_x4(ah[mt], a_hi + off);
                ldsm_x4(al[mt], a_lo + off);
            }
            uint32_t bh[WNT][2], bl[WNT][2];
#pragma unroll
            for (int p = 0; p < WNT / 2; p++) {
                int row = wn * WNT * 8 + p * 16 + br;
                uint32_t off = (uint32_t)(row * LDAe + k16 + bc) * 2;
                uint32_t t[4];
                ldsm_x4(t, b_hi + off);
                bh[2 * p][0] = t[0]; bh[2 * p][1] = t[1];
                bh[2 * p + 1][0] = t[2]; bh[2 * p + 1][1] = t[3];
                ldsm_x4(t, b_lo + off);
                bl[2 * p][0] = t[0]; bl[2 * p][1] = t[1];
                bl[2 * p + 1][0] = t[2]; bl[2 * p + 1][1] = t[3];
            }
#pragma unroll
            for (int mt = 0; mt < WMT; mt++)
#pragma unroll
                for (int nt = 0; nt < WNT; nt++) {
                    mma16816(acc[mt][nt], ah[mt], bh[nt]);
                    mma16816(acc[mt][nt], ah[mt], bl[nt]);
                    mma16816(acc[mt][nt], al[mt], bh[nt]);
                }
        }
        __syncthreads();
    }

    // ---- epilogue A: bias add + fp32 store ----
    const int g  = lane >> 2;
    const int tq = lane & 3;
#pragma unroll
    for (int mt = 0; mt < WMT; mt++) {
        int row = m0 + wm * WMT * 16 + mt * 16 + g;
#pragma unroll
        for (int nt = 0; nt < WNT; nt++) {
            int col = n0 + wn * WNT * 8 + nt * 8 + tq * 2;
            float bx = bias[col], by = bias[col + 1];
            float2 v0 = make_float2(acc[mt][nt][0] + bx, acc[mt][nt][1] + by);
            float2 v1 = make_float2(acc[mt][nt][2] + bx, acc[mt][nt][3] + by);
            *reinterpret_cast<float2*>(&Cout[(size_t)row * Ndim + col]) = v0;
            *reinterpret_cast<float2*>(&Cout[(size_t)(row + 8) * Ndim + col]) = v1;
        }
    }

    // ---- epilogue B: deterministic per-CTA BN stat partials ----
    float2* stats_s = reinterpret_cast<float2*>(smem + OFF_STATS);  // [8][32]
#pragma unroll
    for (int nt = 0; nt < WNT; nt++) {
#pragma unroll
        for (int h = 0; h < 2; h++) {
            int col = n0 + wn * WNT * 8 + nt * 8 + tq * 2 + h;
            float bcol = bias[col];
            float s = 0.0f, q = 0.0f;
#pragma unroll
            for (int mt = 0; mt < WMT; mt++) {
                float v0 = acc[mt][nt][h]     + bcol;
                float v1 = acc[mt][nt][h + 2] + bcol;
                s += v0 + v1;
                q = fmaf(v0, v0, q);
                q = fmaf(v1, v1, q);
            }
#pragma unroll
            for (int off = 4; off < 32; off <<= 1) {
                s += __shfl_xor_sync(0xFFFFFFFFu, s, off);
                q += __shfl_xor_sync(0xFFFFFFFFu, q, off);
            }
            if (lane < 4)
                stats_s[wid * 32 + nt * 8 + lane * 2 + h] = make_float2(s, q);
        }
    }
    __syncthreads();
    if (tid < BN) {
        int wn_ = tid >> 5, jj = tid & 31;
        float s = 0.0f, q = 0.0f;
#pragma unroll
        for (int wm_ = 0; wm_ < WGM; wm_++) {
            float2 v = stats_s[(wm_ * WGN + wn_) * 32 + jj];
            s += v.x;
            q += v.y;
        }
        ps[(size_t)blockIdx.y * Ndim + n0 + tid] = s;
        pq[(size_t)blockIdx.y * Ndim + n0 + tid] = q;
    }
}

// ------------------------- finalize: partials -> (scale, shift) ------------
__global__ void stats_finalize_kernel(const float* __restrict__ ps,
                                      const float* __restrict__ pq, int ncols,
                                      const float* __restrict__ gamma,
                                      const float* __restrict__ beta,
                                      float2* __restrict__ aff) {
    int c = blockIdx.x * 64 + threadIdx.x;
    float s = 0.0f, q = 0.0f;
    for (int i = 0; i < MTILES; i++) {
        s += ps[(size_t)i * ncols + c];
        q += pq[(size_t)i * ncols + c];
    }
    const float inv = 1.0f / (float)Mrows;
    float mean = s * inv;
    float var  = q * inv - mean * mean;
    float sc   = gamma[c] * rsqrtf(var + EPSf);
    aff[c] = make_float2(sc, beta[c] - mean * sc);
}

// ------------------------- BN1+GELU apply + split for GEMM2 A --------------
__global__ void __launch_bounds__(256)
convert_a2_kernel(const float* __restrict__ h1, const float2* __restrict__ aff,
                  __nv_bfloat16* __restrict__ hi, __nv_bfloat16* __restrict__ lo) {
    int idx = blockIdx.x * 256 + threadIdx.x;       // one float4 per thread
    float4 v = reinterpret_cast<const float4*>(h1)[idx];
    int c0 = (idx % (C2c / 4)) * 4;
    float2 a0 = aff[c0 + 0], a1 = aff[c0 + 1], a2 = aff[c0 + 2], a3 = aff[c0 + 3];
    float g0 = gelu_exact(fmaf(v.x, a0.x, a0.y));
    float g1 = gelu_exact(fmaf(v.y, a1.x, a1.y));
    float g2 = gelu_exact(fmaf(v.z, a2.x, a2.y));
    float g3 = gelu_exact(fmaf(v.w, a3.x, a3.y));
    uint2 uh, ul;
    uh.x = pack2(g0, g1, ul.x);
    uh.y = pack2(g2, g3, ul.y);
    reinterpret_cast<uint2*>(hi)[idx] = uh;
    reinterpret_cast<uint2*>(lo)[idx] = ul;
}

// ------------------------- final BN+GELU + NHWC->NCHW ----------------------
__global__ void epilogue_kernel(const float* __restrict__ h2,
                                const float2* __restrict__ aff,
                                float* __restrict__ out) {
    __shared__ float tile[32][33];
    int b  = blockIdx.z;
    int n0 = blockIdx.x * 32;
    int o0 = blockIdx.y * 32;
    int tx = threadIdx.x, ty = threadIdx.y;
    float v  = h2[((size_t)b * Nn + n0 + ty) * OUTc + o0 + tx];
    float2 a = aff[o0 + tx];
    tile[ty][tx] = gelu_exact(fmaf(v, a.x, a.y));
    __syncthreads();
    out[((size_t)b * OUTc + o0 + ty) * Nn + n0 + tx] = tile[tx][ty];
}

// ------------------------- host driver -------------------------------------
extern "C" void kernel_launch(void* const* d_in, const int* in_sizes, int n_in,
                              void* d_out, int out_size) {
    const float* x    = (const float*)d_in[0];
    const int*   edge = (const int*)  d_in[1];
    const float* w1   = (const float*)d_in[2];
    const float* b1   = (const float*)d_in[3];
    const float* g1   = (const float*)d_in[4];
    const float* be1  = (const float*)d_in[5];
    const float* w2   = (const float*)d_in[6];
    const float* b2   = (const float*)d_in[7];
    const float* g2   = (const float*)d_in[8];
    const float* be2  = (const float*)d_in[9];
    float* out = (float*)d_out;

    float *xt, *h1, *h2, *ps, *pq;
    __nv_bfloat16 *a1hi, *a1lo, *a2hi, *a2lo, *w1hi, *w1lo, *w2hi, *w2lo;
    float2 *aff1, *aff2;
    cudaGetSymbolAddress((void**)&xt,   g_xt);
    cudaGetSymbolAddress((void**)&a1hi, g_a1hi);
    cudaGetSymbolAddress((void**)&a1lo, g_a1lo);
    cudaGetSymbolAddress((void**)&a2hi, g_a2hi);
    cudaGetSymbolAddress((void**)&a2lo, g_a2lo);
    cudaGetSymbolAddress((void**)&w1hi, g_w1hi);
    cudaGetSymbolAddress((void**)&w1lo, g_w1lo);
    cudaGetSymbolAddress((void**)&w2hi, g_w2hi);
    cudaGetSymbolAddress((void**)&w2lo, g_w2lo);
    cudaGetSymbolAddress((void**)&h1,   g_h1);
    cudaGetSymbolAddress((void**)&h2,   g_h2);
    cudaGetSymbolAddress((void**)&ps,   g_ps);
    cudaGetSymbolAddress((void**)&pq,   g_pq);
    cudaGetSymbolAddress((void**)&aff1, g_aff1);
    cudaGetSymbolAddress((void**)&aff2, g_aff2);

    // BN=64 config: smem 2048 + 2*(2*10240 + 2*5120) = 63488 per CTA, 3 CTAs/SM
    constexpr int SMEM64 = 2048 + 2 * (2 * 128 * LDAe * 2 + 2 * 64 * LDAe * 2); // 63488
    cudaFuncSetAttribute((const void*)mma_gemm_fused<64, 4, 2, 2, 4, 3>,
                         cudaFuncAttributeMaxDynamicSharedMemorySize, SMEM64);

    dim3 blk32(32, 32);

    // Launch order arranged so GEMM1 is the 4th launch (ncu capture slot).
    // 1) transpose
    transpose_x_kernel<<<dim3(Nn / 32, Cc / 32, Bn), blk32>>>(x, xt);
    // 2) gather + diff-max + interleave, split to bf16 hi/lo
    gather_kernel<<<Mrows / 8, 256>>>(xt, edge, a1hi, a1lo);
    // 3) w1 split
    split_w_kernel<<<(C2c * C2c + 255) / 256, 256>>>(w1, w1hi, w1lo, C2c * C2c);
    // 4) GEMM1 (BN=64, 3 CTA/SM) + fused BN1 stat partials   <-- profiled
    mma_gemm_fused<64, 4, 2, 2, 4, 3>
        <<<dim3(C2c / 64, MTILES), 256, SMEM64>>>(
            a1hi, a1lo, w1hi, w1lo, b1, h1, ps, pq, C2c);
    // 5) BN1 finalize
    stats_finalize_kernel<<<C2c / 64, 64>>>(ps, pq, C2c, g1, be1, aff1);
    // 6) BN1+GELU apply + split -> GEMM2 A operand
    convert_a2_kernel<<<(Mrows * C2c / 4) / 256, 256>>>(h1, aff1, a2hi, a2lo);
    // 7) w2 split
    split_w_kernel<<<(OUTc * C2c + 255) / 256, 256>>>(w2, w2hi, w2lo, OUTc * C2c);
    // 8) GEMM2 (BN=64, 3 CTA/SM) + fused BN2 stat partials
    mma_gemm_fused<64, 4, 2, 2, 4, 3>
        <<<dim3(OUTc / 64, MTILES), 256, SMEM64>>>(
            a2hi, a2lo, w2hi, w2lo, b2, h2, ps, pq, OUTc);
    // 9) BN2 finalize
    stats_finalize_kernel<<<OUTc / 64, 64>>>(ps, pq, OUTc, g2, be2, aff2);
    // 10) final BN+GELU + transpose to [B, OUT, H, W]
    epilogue_kernel<<<dim3(Nn / 32, OUTc / 32, Bn), blk32>>>(h2, aff2, out);
}

// round 13
// speedup vs baseline: 1.4949x; 1.4949x over previous
#include <cuda_runtime.h>
#include <cuda_bf16.h>
#include <cstdint>
#include <math.h>

// Problem constants
#define Bn   8
#define Cc   192
#define Nn   3136          // H*W
#define Kk   9
#define C2c  384           // 2*C
#define OUTc 192
#define Mrows 25088        // B*N
#define MTILES 196         // Mrows / 128
#define EPSf 1e-5f

// ------------------------- device scratch ----------------------------------
__device__ __align__(16) float          g_xt[Bn * Nn * Cc];
__device__ __align__(16) __nv_bfloat16  g_a1hi[(size_t)Mrows * C2c];
__device__ __align__(16) __nv_bfloat16  g_a1lo[(size_t)Mrows * C2c];
__device__ __align__(16) __nv_bfloat16  g_a2hi[(size_t)Mrows * C2c];
__device__ __align__(16) __nv_bfloat16  g_a2lo[(size_t)Mrows * C2c];
__device__ __align__(16) __nv_bfloat16  g_w1hi[C2c * C2c];
__device__ __align__(16) __nv_bfloat16  g_w1lo[C2c * C2c];
__device__ __align__(16) __nv_bfloat16  g_w2hi[OUTc * C2c];
__device__ __align__(16) __nv_bfloat16  g_w2lo[OUTc * C2c];
__device__ __align__(16) float          g_h1[(size_t)Mrows * C2c];
__device__ __align__(16) float          g_h2[(size_t)Mrows * OUTc];
__device__ float  g_ps[MTILES * C2c];
__device__ float  g_pq[MTILES * C2c];
__device__ float2 g_aff1[C2c];
__device__ float2 g_aff2[OUTc];

__device__ __forceinline__ float gelu_exact(float x) {
    return 0.5f * x * (1.0f + erff(x * 0.70710678118654752f));
}
__device__ __forceinline__ void split_bf16(float v, __nv_bfloat16& hi, __nv_bfloat16& lo) {
    hi = __float2bfloat16(v);
    lo = __float2bfloat16(v - __bfloat162float(hi));
}
// pack two floats: returns hi-pair bits, writes lo-pair bits
__device__ __forceinline__ uint32_t pack2(float a, float b, uint32_t& lobits) {
    __nv_bfloat16 h0, l0, h1, l1;
    split_bf16(a, h0, l0);
    split_bf16(b, h1, l1);
    __nv_bfloat162 H; H.x = h0; H.y = h1;
    __nv_bfloat162 L; L.x = l0; L.y = l1;
    lobits = *reinterpret_cast<uint32_t*>(&L);
    return *reinterpret_cast<uint32_t*>(&H);
}
__device__ __forceinline__ uint32_t smem_u32(const void* p) {
    return (uint32_t)__cvta_generic_to_shared(p);
}
__device__ __forceinline__ void ldsm_x4(uint32_t* r, uint32_t addr) {
    asm volatile("ldmatrix.sync.aligned.m8n8.x4.shared.b16 {%0,%1,%2,%3}, [%4];"
                 : "=r"(r[0]), "=r"(r[1]), "=r"(r[2]), "=r"(r[3]) : "r"(addr));
}
__device__ __forceinline__ void mma16816(float* c, const uint32_t* a, const uint32_t* b) {
    asm volatile(
        "mma.sync.aligned.m16n8k16.row.col.f32.bf16.bf16.f32 "
        "{%0,%1,%2,%3}, {%4,%5,%6,%7}, {%8,%9}, {%0,%1,%2,%3};"
        : "+f"(c[0]), "+f"(c[1]), "+f"(c[2]), "+f"(c[3])
        : "r"(a[0]), "r"(a[1]), "r"(a[2]), "r"(a[3]), "r"(b[0]), "r"(b[1]));
}
#define CP16(dst, src)  asm volatile("cp.async.cg.shared.global [%0], [%1], 16;" :: "r"(dst), "l"(src))
#define CP_COMMIT()     asm volatile("cp.async.commit_group;" ::: "memory")
#define CP_WAIT1()      asm volatile("cp.async.wait_group 1;" ::: "memory")
#define CP_WAIT0()      asm volatile("cp.async.wait_group 0;" ::: "memory")

// ------------------------- transpose x -------------------------------------
__global__ void transpose_x_kernel(const float* __restrict__ x, float* __restrict__ xt) {
    __shared__ float tile[32][33];
    int b  = blockIdx.z;
    int n0 = blockIdx.x * 32;
    int c0 = blockIdx.y * 32;
    int tx = threadIdx.x, ty = threadIdx.y;
    tile[ty][tx] = x[((size_t)b * Cc + c0 + ty) * Nn + n0 + tx];
    __syncthreads();
    xt[((size_t)b * Nn + n0 + ty) * Cc + c0 + tx] = tile[tx][ty];
}

// ------------------------- weight split ------------------------------------
__global__ void split_w_kernel(const float* __restrict__ w, __nv_bfloat16* __restrict__ hi,
                               __nv_bfloat16* __restrict__ lo, int n) {
    int i = blockIdx.x * 256 + threadIdx.x;
    if (i < n) split_bf16(w[i], hi[i], lo[i]);
}

// ------------------------- gather + diff-max + interleave + split ----------
__global__ void __launch_bounds__(256)
gather_kernel(const float* __restrict__ xt, const int* __restrict__ edge,
              __nv_bfloat16* __restrict__ ahi, __nv_bfloat16* __restrict__ alo) {
    int warp = (blockIdx.x * blockDim.x + threadIdx.x) >> 5;
    int lane = threadIdx.x & 31;
    int b = warp / Nn;
    int n = warp % Nn;
    const float* xb = xt + (size_t)b * Nn * Cc;

    float xv[6], mv[6];
#pragma unroll
    for (int j = 0; j < 6; j++) {
        xv[j] = xb[(size_t)n * Cc + lane + 32 * j];
        mv[j] = -3.402823466e38f;
    }
    const int* e0 = edge + ((size_t)b * Nn + n) * Kk;
    const int* e1 = e0 + (size_t)Bn * Nn * Kk;
#pragma unroll
    for (int k = 0; k < Kk; k++) {
        int jn  = __ldg(&e0[k]);
        int in_ = __ldg(&e1[k]);
        const float* rj = xb + (size_t)jn  * Cc;
        const float* ri = xb + (size_t)in_ * Cc;
#pragma unroll
        for (int j = 0; j < 6; j++) {
            int c = lane + 32 * j;
            mv[j] = fmaxf(mv[j], __ldg(&rj[c]) - __ldg(&ri[c]));
        }
    }
    __nv_bfloat162* oh = reinterpret_cast<__nv_bfloat162*>(ahi + (size_t)warp * C2c);
    __nv_bfloat162* ol = reinterpret_cast<__nv_bfloat162*>(alo + (size_t)warp * C2c);
#pragma unroll
    for (int j = 0; j < 6; j++) {
        uint32_t lob;
        uint32_t hib = pack2(xv[j], mv[j], lob);
        oh[lane + 32 * j] = *reinterpret_cast<__nv_bfloat162*>(&hib);
        ol[lane + 32 * j] = *reinterpret_cast<__nv_bfloat162*>(&lob);
    }
}

// ------------------------- pipelined mma.sync GEMM + fused BN stats --------
// C[M,Ndim] = A[M,384] * B[Ndim,384]^T + bias; 3-term bf16 split MMA.
// 2-stage cp.async double buffer. Epilogue emits deterministic per-CTA
// (sum, sumsq) partials over its 128 rows for each of its BN columns.
#define GBK  32
#define LDAe 40              // bf16 elems per smem row (32 + 8 pad)

template <int BN, int WGM, int WGN, int WMT, int WNT, int MINB>
__global__ void __launch_bounds__(256, MINB)
mma_gemm_fused(const __nv_bfloat16* __restrict__ Ahi, const __nv_bfloat16* __restrict__ Alo,
               const __nv_bfloat16* __restrict__ Bhi, const __nv_bfloat16* __restrict__ Blo,
               const float* __restrict__ bias, float* __restrict__ Cout,
               float* __restrict__ ps, float* __restrict__ pq, int Ndim) {
    static_assert(WGM * WGN == 8 && WGM * WMT * 16 == 128 && WGN * WNT * 8 == BN, "cfg");
    static_assert(WNT % 2 == 0, "WNT even");
    constexpr int WCOLS = WNT * 8;             // cols per warp
    extern __shared__ __align__(16) char smem[];
    constexpr int AHALF = 128 * LDAe * 2;      // bytes per A half
    constexpr int BHALF = BN  * LDAe * 2;
    constexpr int STAGE = 2 * AHALF + 2 * BHALF;
    constexpr int OFF_STATS = 0;               // float2 [8][WCOLS]
    constexpr int OFF_STG   = 4096;
    constexpr int KITERS = C2c / GBK;          // 12

    const int tid  = threadIdx.x;
    const int wid  = tid >> 5;
    const int lane = tid & 31;
    const int wm   = wid / WGN;
    const int wn   = wid % WGN;
    const int m0   = blockIdx.y * 128;
    const int n0   = blockIdx.x * BN;
    const uint32_t sb = smem_u32(smem);

    float acc[WMT][WNT][4];
#pragma unroll
    for (int i = 0; i < WMT; i++)
#pragma unroll
        for (int j = 0; j < WNT; j++)
#pragma unroll
            for (int q = 0; q < 4; q++) acc[i][j][q] = 0.0f;

    const int ar = lane & 15;
    const int ac = (lane >> 4) << 3;
    const int br = (lane & 7) + ((lane >> 4) << 3);
    const int bc = ((lane >> 3) & 1) << 3;

    auto load_stage = [&](int stg, int kb) {
        const uint32_t a_hi = sb + OFF_STG + stg * STAGE;
        const uint32_t a_lo = a_hi + AHALF;
        const uint32_t b_hi = a_hi + 2 * AHALF;
        const uint32_t b_lo = b_hi + BHALF;
#pragma unroll
        for (int i = 0; i < 2; i++) {                       // A: 512 slots
            int idx = tid + 256 * i;
            int row = idx >> 2, c8 = (idx & 3) << 3;
            size_t  go = (size_t)(m0 + row) * C2c + kb + c8;
            uint32_t so = (uint32_t)(row * LDAe + c8) * 2;
            CP16(a_hi + so, Ahi + go);
            CP16(a_lo + so, Alo + go);
        }
        constexpr int BSLOTS = BN * 4;
#pragma unroll
        for (int i = 0; i < (BSLOTS + 255) / 256; i++) {    // B: BN*4 slots
            int idx = tid + 256 * i;
            if (BSLOTS % 256 == 0 || idx < BSLOTS) {
                int row = idx >> 2, c8 = (idx & 3) << 3;
                size_t  go = (size_t)(n0 + row) * C2c + kb + c8;
                uint32_t so = (uint32_t)(row * LDAe + c8) * 2;
                CP16(b_hi + so, Bhi + go);
                CP16(b_lo + so, Blo + go);
            }
        }
        CP_COMMIT();
    };

    load_stage(0, 0);

    for (int it = 0; it < KITERS; it++) {
        if (it + 1 < KITERS) {
            load_stage((it + 1) & 1, (it + 1) * GBK);
            CP_WAIT1();
        } else {
            CP_WAIT0();
        }
        __syncthreads();

        const int stg = it & 1;
        const uint32_t a_hi = sb + OFF_STG + stg * STAGE;
        const uint32_t a_lo = a_hi + AHALF;
        const uint32_t b_hi = a_hi + 2 * AHALF;
        const uint32_t b_lo = b_hi + BHALF;

#pragma unroll
        for (int ks = 0; ks < 2; ks++) {
            const int k16 = ks * 16;
            uint32_t ah[WMT][4], al[WMT][4];
#pragma unroll
            for (int mt = 0; mt < WMT; mt++) {
                int row = wm * WMT * 16 + mt * 16 + ar;
                uint32_t off = (uint32_t)(row * LDAe + k16 + ac) * 2;
                ldsm_x4(ah[mt], a_hi + off);
                ldsm_x4(al[mt], a_lo + off);
            }
            uint32_t bh[WNT][2], bl[WNT][2];
#pragma unroll
            for (int p = 0; p < WNT / 2; p++) {
                int row = wn * WCOLS + p * 16 + br;
                uint32_t off = (uint32_t)(row * LDAe + k16 + bc) * 2;
                uint32_t t[4];
                ldsm_x4(t, b_hi + off);
                bh[2 * p][0] = t[0]; bh[2 * p][1] = t[1];
                bh[2 * p + 1][0] = t[2]; bh[2 * p + 1][1] = t[3];
                ldsm_x4(t, b_lo + off);
                bl[2 * p][0] = t[0]; bl[2 * p][1] = t[1];
                bl[2 * p + 1][0] = t[2]; bl[2 * p + 1][1] = t[3];
            }
#pragma unroll
            for (int mt = 0; mt < WMT; mt++)
#pragma unroll
                for (int nt = 0; nt < WNT; nt++) {
                    mma16816(acc[mt][nt], ah[mt], bh[nt]);
                    mma16816(acc[mt][nt], ah[mt], bl[nt]);
                    mma16816(acc[mt][nt], al[mt], bh[nt]);
                }
        }
        __syncthreads();
    }

    // ---- epilogue A: bias add + fp32 store ----
    const int g  = lane >> 2;
    const int tq = lane & 3;
#pragma unroll
    for (int mt = 0; mt < WMT; mt++) {
        int row = m0 + wm * WMT * 16 + mt * 16 + g;
#pragma unroll
        for (int nt = 0; nt < WNT; nt++) {
            int col = n0 + wn * WCOLS + nt * 8 + tq * 2;
            float bx = bias[col], by = bias[col + 1];
            float2 v0 = make_float2(acc[mt][nt][0] + bx, acc[mt][nt][1] + by);
            float2 v1 = make_float2(acc[mt][nt][2] + bx, acc[mt][nt][3] + by);
            *reinterpret_cast<float2*>(&Cout[(size_t)row * Ndim + col]) = v0;
            *reinterpret_cast<float2*>(&Cout[(size_t)(row + 8) * Ndim + col]) = v1;
        }
    }

    // ---- epilogue B: deterministic per-CTA BN stat partials ----
    float2* stats_s = reinterpret_cast<float2*>(smem + OFF_STATS);  // [8][WCOLS]
#pragma unroll
    for (int nt = 0; nt < WNT; nt++) {
#pragma unroll
        for (int h = 0; h < 2; h++) {
            int col = n0 + wn * WCOLS + nt * 8 + tq * 2 + h;
            float bcol = bias[col];
            float s = 0.0f, q = 0.0f;
#pragma unroll
            for (int mt = 0; mt < WMT; mt++) {
                float v0 = acc[mt][nt][h]     + bcol;
                float v1 = acc[mt][nt][h + 2] + bcol;
                s += v0 + v1;
                q = fmaf(v0, v0, q);
                q = fmaf(v1, v1, q);
            }
#pragma unroll
            for (int off = 4; off < 32; off <<= 1) {
                s += __shfl_xor_sync(0xFFFFFFFFu, s, off);
                q += __shfl_xor_sync(0xFFFFFFFFu, q, off);
            }
            if (lane < 4)
                stats_s[wid * WCOLS + nt * 8 + lane * 2 + h] = make_float2(s, q);
        }
    }
    __syncthreads();
    if (tid < BN) {
        int wn_ = tid / WCOLS, jj = tid % WCOLS;
        float s = 0.0f, q = 0.0f;
#pragma unroll
        for (int wm_ = 0; wm_ < WGM; wm_++) {
            float2 v = stats_s[(wm_ * WGN + wn_) * WCOLS + jj];
            s += v.x;
            q += v.y;
        }
        ps[(size_t)blockIdx.y * Ndim + n0 + tid] = s;
        pq[(size_t)blockIdx.y * Ndim + n0 + tid] = q;
    }
}

// ------------------------- finalize: partials -> (scale, shift) ------------
__global__ void stats_finalize_kernel(const float* __restrict__ ps,
                                      const float* __restrict__ pq, int ncols,
                                      const float* __restrict__ gamma,
                                      const float* __restrict__ beta,
                                      float2* __restrict__ aff) {
    int c = blockIdx.x * 64 + threadIdx.x;
    float s = 0.0f, q = 0.0f;
    for (int i = 0; i < MTILES; i++) {
        s += ps[(size_t)i * ncols + c];
        q += pq[(size_t)i * ncols + c];
    }
    const float inv = 1.0f / (float)Mrows;
    float mean = s * inv;
    float var  = q * inv - mean * mean;
    float sc   = gamma[c] * rsqrtf(var + EPSf);
    aff[c] = make_float2(sc, beta[c] - mean * sc);
}

// ------------------------- BN1+GELU apply + split for GEMM2 A --------------
__global__ void __launch_bounds__(256)
convert_a2_kernel(const float* __restrict__ h1, const float2* __restrict__ aff,
                  __nv_bfloat16* __restrict__ hi, __nv_bfloat16* __restrict__ lo) {
    int idx = blockIdx.x * 256 + threadIdx.x;       // one float4 per thread
    float4 v = reinterpret_cast<const float4*>(h1)[idx];
    int c0 = (idx % (C2c / 4)) * 4;
    float2 a0 = aff[c0 + 0], a1 = aff[c0 + 1], a2 = aff[c0 + 2], a3 = aff[c0 + 3];
    float g0 = gelu_exact(fmaf(v.x, a0.x, a0.y));
    float g1 = gelu_exact(fmaf(v.y, a1.x, a1.y));
    float g2 = gelu_exact(fmaf(v.z, a2.x, a2.y));
    float g3 = gelu_exact(fmaf(v.w, a3.x, a3.y));
    uint2 uh, ul;
    uh.x = pack2(g0, g1, ul.x);
    uh.y = pack2(g2, g3, ul.y);
    reinterpret_cast<uint2*>(hi)[idx] = uh;
    reinterpret_cast<uint2*>(lo)[idx] = ul;
}

// ------------------------- final BN+GELU + NHWC->NCHW ----------------------
__global__ void epilogue_kernel(const float* __restrict__ h2,
                                const float2* __restrict__ aff,
                                float* __restrict__ out) {
    __shared__ float tile[32][33];
    int b  = blockIdx.z;
    int n0 = blockIdx.x * 32;
    int o0 = blockIdx.y * 32;
    int tx = threadIdx.x, ty = threadIdx.y;
    float v  = h2[((size_t)b * Nn + n0 + ty) * OUTc + o0 + tx];
    float2 a = aff[o0 + tx];
    tile[ty][tx] = gelu_exact(fmaf(v, a.x, a.y));
    __syncthreads();
    out[((size_t)b * OUTc + o0 + ty) * Nn + n0 + tx] = tile[tx][ty];
}

// ------------------------- host driver -------------------------------------
extern "C" void kernel_launch(void* const* d_in, const int* in_sizes, int n_in,
                              void* d_out, int out_size) {
    const float* x    = (const float*)d_in[0];
    const int*   edge = (const int*)  d_in[1];
    const float* w1   = (const float*)d_in[2];
    const float* b1   = (const float*)d_in[3];
    const float* g1   = (const float*)d_in[4];
    const float* be1  = (const float*)d_in[5];
    const float* w2   = (const float*)d_in[6];
    const float* b2   = (const float*)d_in[7];
    const float* g2   = (const float*)d_in[8];
    const float* be2  = (const float*)d_in[9];
    float* out = (float*)d_out;

    float *xt, *h1, *h2, *ps, *pq;
    __nv_bfloat16 *a1hi, *a1lo, *a2hi, *a2lo, *w1hi, *w1lo, *w2hi, *w2lo;
    float2 *aff1, *aff2;
    cudaGetSymbolAddress((void**)&xt,   g_xt);
    cudaGetSymbolAddress((void**)&a1hi, g_a1hi);
    cudaGetSymbolAddress((void**)&a1lo, g_a1lo);
    cudaGetSymbolAddress((void**)&a2hi, g_a2hi);
    cudaGetSymbolAddress((void**)&a2lo, g_a2lo);
    cudaGetSymbolAddress((void**)&w1hi, g_w1hi);
    cudaGetSymbolAddress((void**)&w1lo, g_w1lo);
    cudaGetSymbolAddress((void**)&w2hi, g_w2hi);
    cudaGetSymbolAddress((void**)&w2lo, g_w2lo);
    cudaGetSymbolAddress((void**)&h1,   g_h1);
    cudaGetSymbolAddress((void**)&h2,   g_h2);
    cudaGetSymbolAddress((void**)&ps,   g_ps);
    cudaGetSymbolAddress((void**)&pq,   g_pq);
    cudaGetSymbolAddress((void**)&aff1, g_aff1);
    cudaGetSymbolAddress((void**)&aff2, g_aff2);

    // GEMM1: BN=128 (R11 config, 2 CTA/SM). smem = 4096 + 2*(2*10240+2*10240)
    constexpr int SMEM1 = 4096 + 2 * (2 * 128 * LDAe * 2 + 2 * 128 * LDAe * 2); // 86016
    // GEMM2: BN=96, warp 32x48, 2 CTA/SM. smem = 4096 + 2*(2*10240+2*7680)
    constexpr int SMEM2 = 4096 + 2 * (2 * 128 * LDAe * 2 + 2 * 96 * LDAe * 2);  // 75776
    cudaFuncSetAttribute((const void*)mma_gemm_fused<128, 2, 4, 4, 4, 2>,
                         cudaFuncAttributeMaxDynamicSharedMemorySize, SMEM1);
    cudaFuncSetAttribute((const void*)mma_gemm_fused<96, 4, 2, 2, 6, 2>,
                         cudaFuncAttributeMaxDynamicSharedMemorySize, SMEM2);

    dim3 blk32(32, 32);

    // Launch order arranged so GEMM1 is the 4th launch (ncu capture slot).
    // 1) transpose
    transpose_x_kernel<<<dim3(Nn / 32, Cc / 32, Bn), blk32>>>(x, xt);
    // 2) gather + diff-max + interleave, split to bf16 hi/lo
    gather_kernel<<<Mrows / 8, 256>>>(xt, edge, a1hi, a1lo);
    // 3) w1 split
    split_w_kernel<<<(C2c * C2c + 255) / 256, 256>>>(w1, w1hi, w1lo, C2c * C2c);
    // 4) GEMM1 (BN=128, 2 CTA/SM) + fused BN1 stat partials  <-- profiled
    mma_gemm_fused<128, 2, 4, 4, 4, 2>
        <<<dim3(C2c / 128, MTILES), 256, SMEM1>>>(
            a1hi, a1lo, w1hi, w1lo, b1, h1, ps, pq, C2c);
    // 5) BN1 finalize
    stats_finalize_kernel<<<C2c / 64, 64>>>(ps, pq, C2c, g1, be1, aff1);
    // 6) BN1+GELU apply + split -> GEMM2 A operand
    convert_a2_kernel<<<(Mrows * C2c / 4) / 256, 256>>>(h1, aff1, a2hi, a2lo);
    // 7) w2 split
    split_w_kernel<<<(OUTc * C2c + 255) / 256, 256>>>(w2, w2hi, w2lo, OUTc * C2c);
    // 8) GEMM2 (BN=96, warp 32x48, 2 CTA/SM) + fused BN2 stat partials
    mma_gemm_fused<96, 4, 2, 2, 6, 2>
        <<<dim3(OUTc / 96, MTILES), 256, SMEM2>>>(
            a2hi, a2lo, w2hi, w2lo, b2, h2, ps, pq, OUTc);
    // 9) BN2 finalize
    stats_finalize_kernel<<<OUTc / 64, 64>>>(ps, pq, OUTc, g2, be2, aff2);
    // 10) final BN+GELU + transpose to [B, OUT, H, W]
    epilogue_kernel<<<dim3(Nn / 32, OUTc / 32, Bn), blk32>>>(h2, aff2, out);
}

// round 14
// speedup vs baseline: 1.6382x; 1.0959x over previous
#include <cuda_runtime.h>
#include <cuda_bf16.h>
#include <cstdint>
#include <math.h>

// Problem constants
#define Bn   8
#define Cc   192
#define Nn   3136          // H*W
#define Kk   9
#define C2c  384           // 2*C
#define OUTc 192
#define Mrows 25088        // B*N
#define MT128 196          // Mrows / 128
#define MT256 98           // Mrows / 256
#define EPSf 1e-5f

// ------------------------- device scratch ----------------------------------
__device__ __align__(16) float          g_xt[Bn * Nn * Cc];
__device__ __align__(16) __nv_bfloat16  g_a1hi[(size_t)Mrows * C2c];
__device__ __align__(16) __nv_bfloat16  g_a1lo[(size_t)Mrows * C2c];
__device__ __align__(16) __nv_bfloat16  g_a2hi[(size_t)Mrows * C2c];
__device__ __align__(16) __nv_bfloat16  g_a2lo[(size_t)Mrows * C2c];
__device__ __align__(16) __nv_bfloat16  g_w1hi[C2c * C2c];
__device__ __align__(16) __nv_bfloat16  g_w1lo[C2c * C2c];
__device__ __align__(16) __nv_bfloat16  g_w2hi[OUTc * C2c];
__device__ __align__(16) __nv_bfloat16  g_w2lo[OUTc * C2c];
__device__ __align__(16) float          g_h1[(size_t)Mrows * C2c];
__device__ __align__(16) float          g_h2[(size_t)Mrows * OUTc];
__device__ float  g_ps[MT128 * C2c];
__device__ float  g_pq[MT128 * C2c];
__device__ float2 g_aff1[C2c];
__device__ float2 g_aff2[OUTc];

__device__ __forceinline__ float gelu_exact(float x) {
    return 0.5f * x * (1.0f + erff(x * 0.70710678118654752f));
}
__device__ __forceinline__ void split_bf16(float v, __nv_bfloat16& hi, __nv_bfloat16& lo) {
    hi = __float2bfloat16(v);
    lo = __float2bfloat16(v - __bfloat162float(hi));
}
// pack two floats: returns hi-pair bits, writes lo-pair bits
__device__ __forceinline__ uint32_t pack2(float a, float b, uint32_t& lobits) {
    __nv_bfloat16 h0, l0, h1, l1;
    split_bf16(a, h0, l0);
    split_bf16(b, h1, l1);
    __nv_bfloat162 H; H.x = h0; H.y = h1;
    __nv_bfloat162 L; L.x = l0; L.y = l1;
    lobits = *reinterpret_cast<uint32_t*>(&L);
    return *reinterpret_cast<uint32_t*>(&H);
}
__device__ __forceinline__ uint32_t smem_u32(const void* p) {
    return (uint32_t)__cvta_generic_to_shared(p);
}
__device__ __forceinline__ void ldsm_x4(uint32_t* r, uint32_t addr) {
    asm volatile("ldmatrix.sync.aligned.m8n8.x4.shared.b16 {%0,%1,%2,%3}, [%4];"
                 : "=r"(r[0]), "=r"(r[1]), "=r"(r[2]), "=r"(r[3]) : "r"(addr));
}
__device__ __forceinline__ void mma16816(float* c, const uint32_t* a, const uint32_t* b) {
    asm volatile(
        "mma.sync.aligned.m16n8k16.row.col.f32.bf16.bf16.f32 "
        "{%0,%1,%2,%3}, {%4,%5,%6,%7}, {%8,%9}, {%0,%1,%2,%3};"
        : "+f"(c[0]), "+f"(c[1]), "+f"(c[2]), "+f"(c[3])
        : "r"(a[0]), "r"(a[1]), "r"(a[2]), "r"(a[3]), "r"(b[0]), "r"(b[1]));
}
#define CP16(dst, src)  asm volatile("cp.async.cg.shared.global [%0], [%1], 16;" :: "r"(dst), "l"(src))
#define CP_COMMIT()     asm volatile("cp.async.commit_group;" ::: "memory")
#define CP_WAIT1()      asm volatile("cp.async.wait_group 1;" ::: "memory")
#define CP_WAIT0()      asm volatile("cp.async.wait_group 0;" ::: "memory")

// ------------------------- transpose x -------------------------------------
__global__ void transpose_x_kernel(const float* __restrict__ x, float* __restrict__ xt) {
    __shared__ float tile[32][33];
    int b  = blockIdx.z;
    int n0 = blockIdx.x * 32;
    int c0 = blockIdx.y * 32;
    int tx = threadIdx.x, ty = threadIdx.y;
    tile[ty][tx] = x[((size_t)b * Cc + c0 + ty) * Nn + n0 + tx];
    __syncthreads();
    xt[((size_t)b * Nn + n0 + ty) * Cc + c0 + tx] = tile[tx][ty];
}

// ------------------------- weight split ------------------------------------
__global__ void split_w_kernel(const float* __restrict__ w, __nv_bfloat16* __restrict__ hi,
                               __nv_bfloat16* __restrict__ lo, int n) {
    int i = blockIdx.x * 256 + threadIdx.x;
    if (i < n) split_bf16(w[i], hi[i], lo[i]);
}

// ------------------------- gather + diff-max + interleave + split ----------
__global__ void __launch_bounds__(256)
gather_kernel(const float* __restrict__ xt, const int* __restrict__ edge,
              __nv_bfloat16* __restrict__ ahi, __nv_bfloat16* __restrict__ alo) {
    int warp = (blockIdx.x * blockDim.x + threadIdx.x) >> 5;
    int lane = threadIdx.x & 31;
    int b = warp / Nn;
    int n = warp % Nn;
    const float* xb = xt + (size_t)b * Nn * Cc;

    float xv[6], mv[6];
#pragma unroll
    for (int j = 0; j < 6; j++) {
        xv[j] = xb[(size_t)n * Cc + lane + 32 * j];
        mv[j] = -3.402823466e38f;
    }
    const int* e0 = edge + ((size_t)b * Nn + n) * Kk;
    const int* e1 = e0 + (size_t)Bn * Nn * Kk;
#pragma unroll
    for (int k = 0; k < Kk; k++) {
        int jn  = __ldg(&e0[k]);
        int in_ = __ldg(&e1[k]);
        const float* rj = xb + (size_t)jn  * Cc;
        const float* ri = xb + (size_t)in_ * Cc;
#pragma unroll
        for (int j = 0; j < 6; j++) {
            int c = lane + 32 * j;
            mv[j] = fmaxf(mv[j], __ldg(&rj[c]) - __ldg(&ri[c]));
        }
    }
    __nv_bfloat162* oh = reinterpret_cast<__nv_bfloat162*>(ahi + (size_t)warp * C2c);
    __nv_bfloat162* ol = reinterpret_cast<__nv_bfloat162*>(alo + (size_t)warp * C2c);
#pragma unroll
    for (int j = 0; j < 6; j++) {
        uint32_t lob;
        uint32_t hib = pack2(xv[j], mv[j], lob);
        oh[lane + 32 * j] = *reinterpret_cast<__nv_bfloat162*>(&hib);
        ol[lane + 32 * j] = *reinterpret_cast<__nv_bfloat162*>(&lob);
    }
}

// ------------------------- pipelined mma.sync GEMM + fused BN stats --------
// C[M,Ndim] = A[M,384] * B[Ndim,384]^T + bias; 3-term bf16 split MMA.
// 2-stage cp.async double buffer. Epilogue emits deterministic per-CTA
// (sum, sumsq) partials over its BM rows for each of its BN columns.
#define GBK  32
#define LDAe 40              // bf16 elems per smem row (32 + 8 pad)

template <int BM, int BN, int WGM, int WGN, int WMT, int WNT, int MINB>
__global__ void __launch_bounds__(256, MINB)
mma_gemm_fused(const __nv_bfloat16* __restrict__ Ahi, const __nv_bfloat16* __restrict__ Alo,
               const __nv_bfloat16* __restrict__ Bhi, const __nv_bfloat16* __restrict__ Blo,
               const float* __restrict__ bias, float* __restrict__ Cout,
               float* __restrict__ ps, float* __restrict__ pq, int Ndim) {
    static_assert(WGM * WGN == 8 && WGM * WMT * 16 == BM && WGN * WNT * 8 == BN, "cfg");
    static_assert(WNT % 2 == 0, "WNT even");
    constexpr int WCOLS = WNT * 8;             // cols per warp
    extern __shared__ __align__(16) char smem[];
    constexpr int AHALF = BM * LDAe * 2;       // bytes per A half
    constexpr int BHALF = BN * LDAe * 2;
    constexpr int STAGE = 2 * AHALF + 2 * BHALF;
    constexpr int OFF_STATS = 0;               // float2 [8][WCOLS]
    constexpr int OFF_STG   = 4096;
    constexpr int KITERS = C2c / GBK;          // 12

    const int tid  = threadIdx.x;
    const int wid  = tid >> 5;
    const int lane = tid & 31;
    const int wm   = wid / WGN;
    const int wn   = wid % WGN;
    const int m0   = blockIdx.y * BM;
    const int n0   = blockIdx.x * BN;
    const uint32_t sb = smem_u32(smem);

    float acc[WMT][WNT][4];
#pragma unroll
    for (int i = 0; i < WMT; i++)
#pragma unroll
        for (int j = 0; j < WNT; j++)
#pragma unroll
            for (int q = 0; q < 4; q++) acc[i][j][q] = 0.0f;

    const int ar = lane & 15;
    const int ac = (lane >> 4) << 3;
    const int br = (lane & 7) + ((lane >> 4) << 3);
    const int bc = ((lane >> 3) & 1) << 3;

    auto load_stage = [&](int stg, int kb) {
        const uint32_t a_hi = sb + OFF_STG + stg * STAGE;
        const uint32_t a_lo = a_hi + AHALF;
        const uint32_t b_hi = a_hi + 2 * AHALF;
        const uint32_t b_lo = b_hi + BHALF;
#pragma unroll
        for (int i = 0; i < BM * 4 / 256; i++) {            // A: BM*4 slots
            int idx = tid + 256 * i;
            int row = idx >> 2, c8 = (idx & 3) << 3;
            size_t  go = (size_t)(m0 + row) * C2c + kb + c8;
            uint32_t so = (uint32_t)(row * LDAe + c8) * 2;
            CP16(a_hi + so, Ahi + go);
            CP16(a_lo + so, Alo + go);
        }
        constexpr int BSLOTS = BN * 4;
#pragma unroll
        for (int i = 0; i < (BSLOTS + 255) / 256; i++) {    // B: BN*4 slots
            int idx = tid + 256 * i;
            if (BSLOTS % 256 == 0 || idx < BSLOTS) {
                int row = idx >> 2, c8 = (idx & 3) << 3;
                size_t  go = (size_t)(n0 + row) * C2c + kb + c8;
                uint32_t so = (uint32_t)(row * LDAe + c8) * 2;
                CP16(b_hi + so, Bhi + go);
                CP16(b_lo + so, Blo + go);
            }
        }
        CP_COMMIT();
    };

    load_stage(0, 0);

    for (int it = 0; it < KITERS; it++) {
        if (it + 1 < KITERS) {
            load_stage((it + 1) & 1, (it + 1) * GBK);
            CP_WAIT1();
        } else {
            CP_WAIT0();
        }
        __syncthreads();

        const int stg = it & 1;
        const uint32_t a_hi = sb + OFF_STG + stg * STAGE;
        const uint32_t a_lo = a_hi + AHALF;
        const uint32_t b_hi = a_hi + 2 * AHALF;
        const uint32_t b_lo = b_hi + BHALF;

#pragma unroll
        for (int ks = 0; ks < 2; ks++) {
            const int k16 = ks * 16;
            uint32_t ah[WMT][4], al[WMT][4];
#pragma unroll
            for (int mt = 0; mt < WMT; mt++) {
                int row = wm * WMT * 16 + mt * 16 + ar;
                uint32_t off = (uint32_t)(row * LDAe + k16 + ac) * 2;
                ldsm_x4(ah[mt], a_hi + off);
                ldsm_x4(al[mt], a_lo + off);
            }
            uint32_t bh[WNT][2], bl[WNT][2];
#pragma unroll
            for (int p = 0; p < WNT / 2; p++) {
                int row = wn * WCOLS + p * 16 + br;
                uint32_t off = (uint32_t)(row * LDAe + k16 + bc) * 2;
                uint32_t t[4];
                ldsm_x4(t, b_hi + off);
                bh[2 * p][0] = t[0]; bh[2 * p][1] = t[1];
                bh[2 * p + 1][0] = t[2]; bh[2 * p + 1][1] = t[3];
                ldsm_x4(t, b_lo + off);
                bl[2 * p][0] = t[0]; bl[2 * p][1] = t[1];
                bl[2 * p + 1][0] = t[2]; bl[2 * p + 1][1] = t[3];
            }
#pragma unroll
            for (int mt = 0; mt < WMT; mt++)
#pragma unroll
                for (int nt = 0; nt < WNT; nt++) {
                    mma16816(acc[mt][nt], ah[mt], bh[nt]);
                    mma16816(acc[mt][nt], ah[mt], bl[nt]);
                    mma16816(acc[mt][nt], al[mt], bh[nt]);
                }
        }
        __syncthreads();
    }

    // ---- epilogue A: bias add + fp32 store ----
    const int g  = lane >> 2;
    const int tq = lane & 3;
#pragma unroll
    for (int mt = 0; mt < WMT; mt++) {
        int row = m0 + wm * WMT * 16 + mt * 16 + g;
#pragma unroll
        for (int nt = 0; nt < WNT; nt++) {
            int col = n0 + wn * WCOLS + nt * 8 + tq * 2;
            float bx = bias[col], by = bias[col + 1];
            float2 v0 = make_float2(acc[mt][nt][0] + bx, acc[mt][nt][1] + by);
            float2 v1 = make_float2(acc[mt][nt][2] + bx, acc[mt][nt][3] + by);
            *reinterpret_cast<float2*>(&Cout[(size_t)row * Ndim + col]) = v0;
            *reinterpret_cast<float2*>(&Cout[(size_t)(row + 8) * Ndim + col]) = v1;
        }
    }

    // ---- epilogue B: deterministic per-CTA BN stat partials ----
    float2* stats_s = reinterpret_cast<float2*>(smem + OFF_STATS);  // [8][WCOLS]
#pragma unroll
    for (int nt = 0; nt < WNT; nt++) {
#pragma unroll
        for (int h = 0; h < 2; h++) {
            int col = n0 + wn * WCOLS + nt * 8 + tq * 2 + h;
            float bcol = bias[col];
            float s = 0.0f, q = 0.0f;
#pragma unroll
            for (int mt = 0; mt < WMT; mt++) {
                float v0 = acc[mt][nt][h]     + bcol;
                float v1 = acc[mt][nt][h + 2] + bcol;
                s += v0 + v1;
                q = fmaf(v0, v0, q);
                q = fmaf(v1, v1, q);
            }
#pragma unroll
            for (int off = 4; off < 32; off <<= 1) {
                s += __shfl_xor_sync(0xFFFFFFFFu, s, off);
                q += __shfl_xor_sync(0xFFFFFFFFu, q, off);
            }
            if (lane < 4)
                stats_s[wid * WCOLS + nt * 8 + lane * 2 + h] = make_float2(s, q);
        }
    }
    __syncthreads();
    if (tid < BN) {
        int wn_ = tid / WCOLS, jj = tid % WCOLS;
        float s = 0.0f, q = 0.0f;
#pragma unroll
        for (int wm_ = 0; wm_ < WGM; wm_++) {
            float2 v = stats_s[(wm_ * WGN + wn_) * WCOLS + jj];
            s += v.x;
            q += v.y;
        }
        ps[(size_t)blockIdx.y * Ndim + n0 + tid] = s;
        pq[(size_t)blockIdx.y * Ndim + n0 + tid] = q;
    }
}

// ------------------------- finalize: partials -> (scale, shift) ------------
__global__ void stats_finalize_kernel(const float* __restrict__ ps,
                                      const float* __restrict__ pq, int ncols,
                                      int ntiles,
                                      const float* __restrict__ gamma,
                                      const float* __restrict__ beta,
                                      float2* __restrict__ aff) {
    int c = blockIdx.x * 64 + threadIdx.x;
    float s = 0.0f, q = 0.0f;
    for (int i = 0; i < ntiles; i++) {
        s += ps[(size_t)i * ncols + c];
        q += pq[(size_t)i * ncols + c];
    }
    const float inv = 1.0f / (float)Mrows;
    float mean = s * inv;
    float var  = q * inv - mean * mean;
    float sc   = gamma[c] * rsqrtf(var + EPSf);
    aff[c] = make_float2(sc, beta[c] - mean * sc);
}

// ------------------------- BN1+GELU apply + split for GEMM2 A --------------
__global__ void __launch_bounds__(256)
convert_a2_kernel(const float* __restrict__ h1, const float2* __restrict__ aff,
                  __nv_bfloat16* __restrict__ hi, __nv_bfloat16* __restrict__ lo) {
    int idx = blockIdx.x * 256 + threadIdx.x;       // one float4 per thread
    float4 v = reinterpret_cast<const float4*>(h1)[idx];
    int c0 = (idx % (C2c / 4)) * 4;
    float2 a0 = aff[c0 + 0], a1 = aff[c0 + 1], a2 = aff[c0 + 2], a3 = aff[c0 + 3];
    float g0 = gelu_exact(fmaf(v.x, a0.x, a0.y));
    float g1 = gelu_exact(fmaf(v.y, a1.x, a1.y));
    float g2 = gelu_exact(fmaf(v.z, a2.x, a2.y));
    float g3 = gelu_exact(fmaf(v.w, a3.x, a3.y));
    uint2 uh, ul;
    uh.x = pack2(g0, g1, ul.x);
    uh.y = pack2(g2, g3, ul.y);
    reinterpret_cast<uint2*>(hi)[idx] = uh;
    reinterpret_cast<uint2*>(lo)[idx] = ul;
}

// ------------------------- final BN+GELU + NHWC->NCHW ----------------------
__global__ void epilogue_kernel(const float* __restrict__ h2,
                                const float2* __restrict__ aff,
                                float* __restrict__ out) {
    __shared__ float tile[32][33];
    int b  = blockIdx.z;
    int n0 = blockIdx.x * 32;
    int o0 = blockIdx.y * 32;
    int tx = threadIdx.x, ty = threadIdx.y;
    float v  = h2[((size_t)b * Nn + n0 + ty) * OUTc + o0 + tx];
    float2 a = aff[o0 + tx];
    tile[ty][tx] = gelu_exact(fmaf(v, a.x, a.y));
    __syncthreads();
    out[((size_t)b * OUTc + o0 + ty) * Nn + n0 + tx] = tile[tx][ty];
}

// ------------------------- host driver -------------------------------------
extern "C" void kernel_launch(void* const* d_in, const int* in_sizes, int n_in,
                              void* d_out, int out_size) {
    const float* x    = (const float*)d_in[0];
    const int*   edge = (const int*)  d_in[1];
    const float* w1   = (const float*)d_in[2];
    const float* b1   = (const float*)d_in[3];
    const float* g1   = (const float*)d_in[4];
    const float* be1  = (const float*)d_in[5];
    const float* w2   = (const float*)d_in[6];
    const float* b2   = (const float*)d_in[7];
    const float* g2   = (const float*)d_in[8];
    const float* be2  = (const float*)d_in[9];
    float* out = (float*)d_out;

    float *xt, *h1, *h2, *ps, *pq;
    __nv_bfloat16 *a1hi, *a1lo, *a2hi, *a2lo, *w1hi, *w1lo, *w2hi, *w2lo;
    float2 *aff1, *aff2;
    cudaGetSymbolAddress((void**)&xt,   g_xt);
    cudaGetSymbolAddress((void**)&a1hi, g_a1hi);
    cudaGetSymbolAddress((void**)&a1lo, g_a1lo);
    cudaGetSymbolAddress((void**)&a2hi, g_a2hi);
    cudaGetSymbolAddress((void**)&a2lo, g_a2lo);
    cudaGetSymbolAddress((void**)&w1hi, g_w1hi);
    cudaGetSymbolAddress((void**)&w1lo, g_w1lo);
    cudaGetSymbolAddress((void**)&w2hi, g_w2hi);
    cudaGetSymbolAddress((void**)&w2lo, g_w2lo);
    cudaGetSymbolAddress((void**)&h1,   g_h1);
    cudaGetSymbolAddress((void**)&h2,   g_h2);
    cudaGetSymbolAddress((void**)&ps,   g_ps);
    cudaGetSymbolAddress((void**)&pq,   g_pq);
    cudaGetSymbolAddress((void**)&aff1, g_aff1);
    cudaGetSymbolAddress((void**)&aff2, g_aff2);

    // GEMM1: BM=128, BN=128, 2 CTA/SM.  smem = 4096 + 2*(2*10240 + 2*10240)
    constexpr int SMEM1 = 4096 + 2 * (2 * 128 * LDAe * 2 + 2 * 128 * LDAe * 2); // 86016
    // GEMM2: BM=256, BN=64, 2 CTA/SM.   smem = 4096 + 2*(2*20480 + 2*5120)
    constexpr int SMEM2 = 4096 + 2 * (2 * 256 * LDAe * 2 + 2 * 64 * LDAe * 2);  // 106496
    cudaFuncSetAttribute((const void*)mma_gemm_fused<128, 128, 2, 4, 4, 4, 2>,
                         cudaFuncAttributeMaxDynamicSharedMemorySize, SMEM1);
    cudaFuncSetAttribute((const void*)mma_gemm_fused<256, 64, 4, 2, 4, 4, 2>,
                         cudaFuncAttributeMaxDynamicSharedMemorySize, SMEM2);

    dim3 blk32(32, 32);

    // Launch order arranged so GEMM1 is the 4th launch (ncu capture slot).
    // 1) transpose
    transpose_x_kernel<<<dim3(Nn / 32, Cc / 32, Bn), blk32>>>(x, xt);
    // 2) gather + diff-max + interleave, split to bf16 hi/lo
    gather_kernel<<<Mrows / 8, 256>>>(xt, edge, a1hi, a1lo);
    // 3) w1 split
    split_w_kernel<<<(C2c * C2c + 255) / 256, 256>>>(w1, w1hi, w1lo, C2c * C2c);
    // 4) GEMM1 (BM=128, BN=128) + fused BN1 stat partials   <-- profiled
    mma_gemm_fused<128, 128, 2, 4, 4, 4, 2>
        <<<dim3(C2c / 128, MT128), 256, SMEM1>>>(
            a1hi, a1lo, w1hi, w1lo, b1, h1, ps, pq, C2c);
    // 5) BN1 finalize (196 tiles)
    stats_finalize_kernel<<<C2c / 64, 64>>>(ps, pq, C2c, MT128, g1, be1, aff1);
    // 6) BN1+GELU apply + split -> GEMM2 A operand
    convert_a2_kernel<<<(Mrows * C2c / 4) / 256, 256>>>(h1, aff1, a2hi, a2lo);
    // 7) w2 split
    split_w_kernel<<<(OUTc * C2c + 255) / 256, 256>>>(w2, w2hi, w2lo, OUTc * C2c);
    // 8) GEMM2 (BM=256, BN=64; grid 294 = single wave) + BN2 stat partials
    mma_gemm_fused<256, 64, 4, 2, 4, 4, 2>
        <<<dim3(OUTc / 64, MT256), 256, SMEM2>>>(
            a2hi, a2lo, w2hi, w2lo, b2, h2, ps, pq, OUTc);
    // 9) BN2 finalize (98 tiles)
    stats_finalize_kernel<<<OUTc / 64, 64>>>(ps, pq, OUTc, MT256, g2, be2, aff2);
    // 10) final BN+GELU + transpose to [B, OUT, H, W]
    epilogue_kernel<<<dim3(Nn / 32, OUTc / 32, Bn), blk32>>>(h2, aff2, out);
}